// round 12
// baseline (speedup 1.0000x reference)
#include <cuda_runtime.h>
#include <cuda_bf16.h>
#include <math.h>
#include <cstdint>

#define NB 16
#define S1 512
#define S2 40
#define DV 1024
#define DT 300
#define DA 256
#define DO 500
#define DO_PAD 512

// ---------------------------------------------------------------------------
// Scratch (static device globals: allocation-free)
// ---------------------------------------------------------------------------
__device__ float g_f[NB * S2 * DA];                    // f = text @ w2    (16,40,256)
__device__ float g_e[NB * S1 * DA];                    // e = video @ w1   (16,512,256)
__device__ __nv_bfloat16 g_vh[NB * S1 * DV];           // video split hi
__device__ __nv_bfloat16 g_vl[NB * S1 * DV];           // video split lo
__device__ __nv_bfloat16 g_gh[NB * S1 * 4 * DA];       // tanh(cont) split hi
__device__ __nv_bfloat16 g_gl[NB * S1 * 4 * DA];       // tanh(cont) split lo
__device__ __nv_bfloat16 g_w1h[DA * DV];               // w1^T hi [256,1024]
__device__ __nv_bfloat16 g_w1l[DA * DV];               // w1^T lo
__device__ __nv_bfloat16 g_w4h[DO_PAD * (4 * DA)];     // w4^T hi [512,1024] (rows>=500 zero)
__device__ __nv_bfloat16 g_w4l[DO_PAD * (4 * DA)];     // w4^T lo

// ---------------------------------------------------------------------------
// Fast accurate tanh: 2 MUFU + ~5 ALU, rel err ~1e-6
// ---------------------------------------------------------------------------
__device__ __forceinline__ float fast_tanh(float x) {
    float ax = fabsf(x);
    float e = __expf(-2.f * ax);
    float t = __fdividef(1.f - e, 1.f + e);
    return copysignf(t, x);
}

// mma.sync m16n8k16 bf16 (sm_80+ base feature; NOT arch-specific)
#define MMA16816(c, a0, a1, a2, a3, b0, b1)                                  \
    asm volatile(                                                            \
        "mma.sync.aligned.m16n8k16.row.col.f32.bf16.bf16.f32 "               \
        "{%0,%1,%2,%3}, {%4,%5,%6,%7}, {%8,%9}, {%0,%1,%2,%3};"              \
        : "+f"((c)[0]), "+f"((c)[1]), "+f"((c)[2]), "+f"((c)[3])             \
        : "r"(a0), "r"(a1), "r"(a2), "r"(a3), "r"(b0), "r"(b1))

__device__ __forceinline__ void split2(float v, __nv_bfloat16& h, __nv_bfloat16& l) {
    h = __float2bfloat16(v);
    l = __float2bfloat16(v - __bfloat162float(h));
}

// ---------------------------------------------------------------------------
// k_pre: fused prologue — one launch, four independent jobs by block range.
// ---------------------------------------------------------------------------
#define NBLK_W1 ((DA * DV) / 256)               // 1024
#define NBLK_W4 ((DO_PAD * 4 * DA) / 256)       // 2048
#define NBLK_V  ((NB * S1 * DV / 4) / 256)      // 8192
#define NBLK_T  (NB * S2)                       // 640

__global__ __launch_bounds__(256) void k_pre(const float* __restrict__ w1,
                                             const float* __restrict__ w4,
                                             const float* __restrict__ video,
                                             const float* __restrict__ text,
                                             const float* __restrict__ w2) {
    __shared__ float ts[DT];
    int bid = blockIdx.x, tid = threadIdx.x;

    if (bid < NBLK_W1) {
        int idx = bid * 256 + tid;
        int n = idx >> 10, k = idx & (DV - 1);
        float v = w1[(long)k * DA + n];
        split2(v, g_w1h[idx], g_w1l[idx]);
    } else if (bid < NBLK_W1 + NBLK_W4) {
        int idx = (bid - NBLK_W1) * 256 + tid;
        int n = idx >> 10, k = idx & (4 * DA - 1);
        float v = (n < DO) ? w4[(long)k * DO + n] : 0.f;
        split2(v, g_w4h[idx], g_w4l[idx]);
    } else if (bid < NBLK_W1 + NBLK_W4 + NBLK_V) {
        int i = (bid - NBLK_W1 - NBLK_W4) * 256 + tid;
        float4 v = ((const float4*)video)[i];
        __nv_bfloat16 hh[4], ll[4];
        split2(v.x, hh[0], ll[0]);
        split2(v.y, hh[1], ll[1]);
        split2(v.z, hh[2], ll[2]);
        split2(v.w, hh[3], ll[3]);
        *(uint2*)&g_vh[4 * i] = *(uint2*)hh;
        *(uint2*)&g_vl[4 * i] = *(uint2*)ll;
    } else {
        int row = bid - (NBLK_W1 + NBLK_W4 + NBLK_V);
        for (int i = tid; i < DT; i += 256)
            ts[i] = text[row * DT + i];
        __syncthreads();

        float a0 = 0.f, a1 = 0.f, a2 = 0.f, a3 = 0.f;
        const float* w2p = w2 + tid;
        #pragma unroll 5
        for (int d = 0; d < DT; d += 4) {
            a0 += ts[d]     * w2p[(d)     * DA];
            a1 += ts[d + 1] * w2p[(d + 1) * DA];
            a2 += ts[d + 2] * w2p[(d + 2) * DA];
            a3 += ts[d + 3] * w2p[(d + 3) * DA];
        }
        g_f[row * DA + tid] = (a0 + a1) + (a2 + a3);
    }
}

// ---------------------------------------------------------------------------
// Tensor-core GEMM via mma.sync: C[M,N] = A @ Bt^T (+bias), split-bf16.
// CTA tile 128(M)x64(N), 256 threads / 8 warps in 4(M)x2(N); warp tile 32x32
// via 2x4 m16n8k16 tiles x 3 split-products. Double-buffered smem (61 KB),
// __launch_bounds__(256, 2) => 2 CTAs/SM co-resident for cross-CTA overlap
// of LDS/STS phases with tensor phases.
// ---------------------------------------------------------------------------
#define PITCH 40                  // bf16 units per smem row (32 + 8 pad)
#define OFF_AL (128 * PITCH)      // 5120
#define OFF_BH (2 * 128 * PITCH)  // 10240
#define OFF_BL (OFF_BH + 64 * PITCH)  // 12800
#define SSTG  (OFF_BL + 64 * PITCH)   // 15360 bf16 per stage
#define GSMEM (2 * SSTG * (int)sizeof(__nv_bfloat16))   // 61440 B

__global__ void __launch_bounds__(256, 2) k_gemm_mma(
    const __nv_bfloat16* __restrict__ Ah, const __nv_bfloat16* __restrict__ Al,
    const __nv_bfloat16* __restrict__ Bh, const __nv_bfloat16* __restrict__ Bl,
    const float* __restrict__ bias, float* __restrict__ C, int N, int K) {
    extern __shared__ __nv_bfloat16 sm[];

    int tid = threadIdx.x, lane = tid & 31, wid = tid >> 5;
    int g = lane >> 2, tg = lane & 3;
    int brow = blockIdx.x * 128, bn = blockIdx.y * 64;
    int wm = (wid >> 1) * 32, wn = (wid & 1) * 32;

    float acc[2][4][4];
    #pragma unroll
    for (int mi = 0; mi < 2; mi++)
        #pragma unroll
        for (int ni = 0; ni < 4; ni++)
            #pragma unroll
            for (int q = 0; q < 4; q++) acc[mi][ni][q] = 0.f;

    int lrow = tid >> 2;   // 0..63
    int lseg = tid & 3;    // 8-bf16 segment

    uint4 ra_h[2], ra_l[2], rb_h, rb_l;

    // LDG chunk 0
    #pragma unroll
    for (int it = 0; it < 2; it++) {
        long ga = (long)(brow + it * 64 + lrow) * K + lseg * 8;
        ra_h[it] = *(const uint4*)&Ah[ga];
        ra_l[it] = *(const uint4*)&Al[ga];
    }
    {
        long gb = (long)(bn + lrow) * K + lseg * 8;
        rb_h = *(const uint4*)&Bh[gb];
        rb_l = *(const uint4*)&Bl[gb];
    }
    // STS chunk 0 -> stage 0
    #pragma unroll
    for (int it = 0; it < 2; it++) {
        int so = (it * 64 + lrow) * PITCH + lseg * 8;
        *(uint4*)&sm[so] = ra_h[it];
        *(uint4*)&sm[OFF_AL + so] = ra_l[it];
    }
    {
        int so = lrow * PITCH + lseg * 8;
        *(uint4*)&sm[OFF_BH + so] = rb_h;
        *(uint4*)&sm[OFF_BL + so] = rb_l;
    }
    __syncthreads();

    int cur = 0;
    for (int kc = 0; kc < K; kc += 32) {
        bool has_next = (kc + 32 < K);
        if (has_next) {
            #pragma unroll
            for (int it = 0; it < 2; it++) {
                long ga = (long)(brow + it * 64 + lrow) * K + kc + 32 + lseg * 8;
                ra_h[it] = *(const uint4*)&Ah[ga];
                ra_l[it] = *(const uint4*)&Al[ga];
            }
            long gb = (long)(bn + lrow) * K + kc + 32 + lseg * 8;
            rb_h = *(const uint4*)&Bh[gb];
            rb_l = *(const uint4*)&Bl[gb];
        }

        const __nv_bfloat16* sAh = sm + cur * SSTG;
        const __nv_bfloat16* sAl = sAh + OFF_AL;
        const __nv_bfloat16* sBh = sAh + OFF_BH;
        const __nv_bfloat16* sBl = sAh + OFF_BL;

        #pragma unroll
        for (int ks = 0; ks < 2; ks++) {
            int kb = ks * 16 + 2 * tg;
            uint32_t bh0[4], bh1[4], bl0[4], bl1[4];
            #pragma unroll
            for (int ni = 0; ni < 4; ni++) {
                int br = (wn + ni * 8 + g) * PITCH;
                bh0[ni] = *(const uint32_t*)&sBh[br + kb];
                bh1[ni] = *(const uint32_t*)&sBh[br + kb + 8];
                bl0[ni] = *(const uint32_t*)&sBl[br + kb];
                bl1[ni] = *(const uint32_t*)&sBl[br + kb + 8];
            }
            #pragma unroll
            for (int mi = 0; mi < 2; mi++) {
                int ar0 = (wm + mi * 16 + g) * PITCH;
                int ar1 = ar0 + 8 * PITCH;
                uint32_t ah0 = *(const uint32_t*)&sAh[ar0 + kb];
                uint32_t ah1 = *(const uint32_t*)&sAh[ar1 + kb];
                uint32_t ah2 = *(const uint32_t*)&sAh[ar0 + kb + 8];
                uint32_t ah3 = *(const uint32_t*)&sAh[ar1 + kb + 8];
                uint32_t al0 = *(const uint32_t*)&sAl[ar0 + kb];
                uint32_t al1 = *(const uint32_t*)&sAl[ar1 + kb];
                uint32_t al2 = *(const uint32_t*)&sAl[ar0 + kb + 8];
                uint32_t al3 = *(const uint32_t*)&sAl[ar1 + kb + 8];
                // product sweep: consecutive MMAs hit different accumulators
                #pragma unroll
                for (int ni = 0; ni < 4; ni++)
                    MMA16816(acc[mi][ni], ah0, ah1, ah2, ah3, bh0[ni], bh1[ni]);
                #pragma unroll
                for (int ni = 0; ni < 4; ni++)
                    MMA16816(acc[mi][ni], ah0, ah1, ah2, ah3, bl0[ni], bl1[ni]);
                #pragma unroll
                for (int ni = 0; ni < 4; ni++)
                    MMA16816(acc[mi][ni], al0, al1, al2, al3, bh0[ni], bh1[ni]);
            }
        }

        if (has_next) {
            int nxt = cur ^ 1;
            __nv_bfloat16* d = sm + nxt * SSTG;
            #pragma unroll
            for (int it = 0; it < 2; it++) {
                int so = (it * 64 + lrow) * PITCH + lseg * 8;
                *(uint4*)&d[so] = ra_h[it];
                *(uint4*)&d[OFF_AL + so] = ra_l[it];
            }
            int so = lrow * PITCH + lseg * 8;
            *(uint4*)&d[OFF_BH + so] = rb_h;
            *(uint4*)&d[OFF_BL + so] = rb_l;
            __syncthreads();
            cur = nxt;
        }
    }

    #pragma unroll
    for (int mi = 0; mi < 2; mi++) {
        int row = brow + wm + mi * 16 + g;
        #pragma unroll
        for (int ni = 0; ni < 4; ni++) {
            int col = bn + wn + ni * 8 + 2 * tg;
            if (col < N) {
                float b0 = bias ? bias[col] : 0.f;
                float b1 = bias ? bias[col + 1] : 0.f;
                *(float2*)&C[(long)row * N + col] =
                    make_float2(acc[mi][ni][0] + b0, acc[mi][ni][1] + b1);
                *(float2*)&C[(long)(row + 8) * N + col] =
                    make_float2(acc[mi][ni][2] + b0, acc[mi][ni][3] + b1);
            }
        }
    }
}

// ---------------------------------------------------------------------------
// k_attn: fused attention; 16 rows per block.
// ---------------------------------------------------------------------------
#define ROWS_PER_BLK 16

__global__ __launch_bounds__(256) void k_attn(const float* __restrict__ w3,
                                              const float* __restrict__ bias) {
    __shared__ float fb[S2 * DA];
    __shared__ float es[DA];
    __shared__ float w3s[DA];
    __shared__ float bs[DA];
    __shared__ float sc[S2];
    __shared__ float inv_s;

    int tid = threadIdx.x;
    int b = blockIdx.x, s0 = blockIdx.y * ROWS_PER_BLK;
    int warp = tid >> 5, lane = tid & 31;

    w3s[tid] = w3[tid];
    bs[tid] = bias[tid];
    __syncthreads();
    for (int i = tid; i < S2 * DA; i += 256)
        fb[i] = g_f[b * S2 * DA + i] + bs[i & (DA - 1)];

    for (int r = 0; r < ROWS_PER_BLK; r++) {
        int s = s0 + r;
        __syncthreads();
        es[tid] = g_e[((long)b * S1 + s) * DA + tid];
        __syncthreads();

        #pragma unroll
        for (int tt = 0; tt < 5; tt++) {
            int t = warp + 8 * tt;
            float p = 0.f;
            #pragma unroll
            for (int j = 0; j < 8; j++) {
                int a = lane + 32 * j;
                p += fast_tanh(es[a] + fb[t * DA + a]) * w3s[a];
            }
            #pragma unroll
            for (int off = 16; off; off >>= 1)
                p += __shfl_xor_sync(0xffffffffu, p, off);
            if (lane == 0) sc[t] = p;
        }
        __syncthreads();

        if (warp == 0) {
            float v0 = sc[lane];
            float v1 = (lane + 32 < S2) ? sc[lane + 32] : -3.4e38f;
            float m = fmaxf(v0, v1);
            #pragma unroll
            for (int off = 16; off; off >>= 1)
                m = fmaxf(m, __shfl_xor_sync(0xffffffffu, m, off));
            float e0 = __expf(v0 - m);
            float e1 = (lane + 32 < S2) ? __expf(v1 - m) : 0.f;
            float su = e0 + e1;
            #pragma unroll
            for (int off = 16; off; off >>= 1)
                su += __shfl_xor_sync(0xffffffffu, su, off);
            sc[lane] = e0;
            if (lane + 32 < S2) sc[lane + 32] = e1;
            if (lane == 0) inv_s = 1.f / su;
        }
        __syncthreads();

        float acc = 0.f;
        #pragma unroll 8
        for (int t = 0; t < S2; t++)
            acc += sc[t] * fb[t * DA + tid];
        float ta = acc * inv_s - bs[tid];
        float ev = es[tid];

        long go = ((long)b * S1 + s) * (4 * DA) + tid;
        float vals[4] = {fast_tanh(ev), fast_tanh(ta),
                         fast_tanh(ev * ta), fast_tanh(ev - ta)};
        #pragma unroll
        for (int q = 0; q < 4; q++) {
            __nv_bfloat16 h = __float2bfloat16(vals[q]);
            g_gh[go + q * DA] = h;
            g_gl[go + q * DA] = __float2bfloat16(vals[q] - __bfloat162float(h));
        }
    }
}

// ---------------------------------------------------------------------------
extern "C" void kernel_launch(void* const* d_in, const int* in_sizes, int n_in,
                              void* d_out, int out_size) {
    const float* video = (const float*)d_in[0];
    const float* text  = (const float*)d_in[1];
    const float* w1    = (const float*)d_in[2];
    const float* w2    = (const float*)d_in[3];
    const float* w3    = (const float*)d_in[4];
    const float* bias  = (const float*)d_in[5];
    const float* w4    = (const float*)d_in[6];
    const float* b4    = (const float*)d_in[7];
    float* out = (float*)d_out;

    float* pe;
    __nv_bfloat16 *pvh, *pvl, *pgh, *pgl, *p1h, *p1l, *p4h, *p4l;
    cudaGetSymbolAddress((void**)&pe, g_e);
    cudaGetSymbolAddress((void**)&pvh, g_vh);
    cudaGetSymbolAddress((void**)&pvl, g_vl);
    cudaGetSymbolAddress((void**)&pgh, g_gh);
    cudaGetSymbolAddress((void**)&pgl, g_gl);
    cudaGetSymbolAddress((void**)&p1h, g_w1h);
    cudaGetSymbolAddress((void**)&p1l, g_w1l);
    cudaGetSymbolAddress((void**)&p4h, g_w4h);
    cudaGetSymbolAddress((void**)&p4l, g_w4l);

    cudaFuncSetAttribute(k_gemm_mma, cudaFuncAttributeMaxDynamicSharedMemorySize,
                         GSMEM);

    // fused prologue
    k_pre<<<NBLK_W1 + NBLK_W4 + NBLK_V + NBLK_T, 256>>>(w1, w4, video, text, w2);
    // e = video @ w1  (8192x256, K=1024): grid 64x4 = 256 CTAs
    k_gemm_mma<<<dim3((NB * S1) / 128, DA / 64), 256, GSMEM>>>(
        pvh, pvl, p1h, p1l, nullptr, pe, DA, DV);
    // fused attention -> g (split bf16)
    k_attn<<<dim3(NB, S1 / ROWS_PER_BLK), 256>>>(w3, bias);
    // out = g @ w4 + b4  (8192x500, K=1024): grid 64x8 = 512 CTAs
    k_gemm_mma<<<dim3((NB * S1) / 128, DO_PAD / 64), 256, GSMEM>>>(
        pgh, pgl, p4h, p4l, b4, out, DO, 4 * DA);
}

// round 13
// speedup vs baseline: 1.0483x; 1.0483x over previous
#include <cuda_runtime.h>
#include <cuda_bf16.h>
#include <math.h>
#include <cstdint>

#define NB 16
#define S1 512
#define S2 40
#define DV 1024
#define DT 300
#define DA 256
#define DO 500
#define DO_PAD 512

// ---------------------------------------------------------------------------
// Scratch (static device globals: allocation-free)
// ---------------------------------------------------------------------------
__device__ float g_f[NB * S2 * DA];                    // f = text @ w2    (16,40,256)
__device__ float g_e[NB * S1 * DA];                    // e = video @ w1   (16,512,256)
__device__ __nv_bfloat16 g_vh[NB * S1 * DV];           // video split hi
__device__ __nv_bfloat16 g_vl[NB * S1 * DV];           // video split lo
__device__ __nv_bfloat16 g_gh[NB * S1 * 4 * DA];       // tanh(cont) split hi
__device__ __nv_bfloat16 g_gl[NB * S1 * 4 * DA];       // tanh(cont) split lo
__device__ __nv_bfloat16 g_w1h[DA * DV];               // w1^T hi [256,1024]
__device__ __nv_bfloat16 g_w1l[DA * DV];               // w1^T lo
__device__ __nv_bfloat16 g_w4h[DO_PAD * (4 * DA)];     // w4^T hi [512,1024] (rows>=500 zero)
__device__ __nv_bfloat16 g_w4l[DO_PAD * (4 * DA)];     // w4^T lo

// ---------------------------------------------------------------------------
// Fast accurate tanh: 2 MUFU + ~5 ALU, rel err ~1e-6
// ---------------------------------------------------------------------------
__device__ __forceinline__ float fast_tanh(float x) {
    float ax = fabsf(x);
    float e = __expf(-2.f * ax);
    float t = __fdividef(1.f - e, 1.f + e);
    return copysignf(t, x);
}

// mma.sync m16n8k16 bf16 (sm_80+ base feature; NOT arch-specific)
#define MMA16816(c, a0, a1, a2, a3, b0, b1)                                  \
    asm volatile(                                                            \
        "mma.sync.aligned.m16n8k16.row.col.f32.bf16.bf16.f32 "               \
        "{%0,%1,%2,%3}, {%4,%5,%6,%7}, {%8,%9}, {%0,%1,%2,%3};"              \
        : "+f"((c)[0]), "+f"((c)[1]), "+f"((c)[2]), "+f"((c)[3])             \
        : "r"(a0), "r"(a1), "r"(a2), "r"(a3), "r"(b0), "r"(b1))

__device__ __forceinline__ void split2(float v, __nv_bfloat16& h, __nv_bfloat16& l) {
    h = __float2bfloat16(v);
    l = __float2bfloat16(v - __bfloat162float(h));
}

// ---------------------------------------------------------------------------
// k_pre: fused prologue — one launch, four independent jobs by block range.
// ---------------------------------------------------------------------------
#define NBLK_W1 ((DA * DV) / 256)               // 1024
#define NBLK_W4 ((DO_PAD * 4 * DA) / 256)       // 2048
#define NBLK_V  ((NB * S1 * DV / 4) / 256)      // 8192
#define NBLK_T  (NB * S2)                       // 640

__global__ __launch_bounds__(256) void k_pre(const float* __restrict__ w1,
                                             const float* __restrict__ w4,
                                             const float* __restrict__ video,
                                             const float* __restrict__ text,
                                             const float* __restrict__ w2) {
    __shared__ float ts[DT];
    int bid = blockIdx.x, tid = threadIdx.x;

    if (bid < NBLK_W1) {
        int idx = bid * 256 + tid;
        int n = idx >> 10, k = idx & (DV - 1);
        float v = w1[(long)k * DA + n];
        split2(v, g_w1h[idx], g_w1l[idx]);
    } else if (bid < NBLK_W1 + NBLK_W4) {
        int idx = (bid - NBLK_W1) * 256 + tid;
        int n = idx >> 10, k = idx & (4 * DA - 1);
        float v = (n < DO) ? w4[(long)k * DO + n] : 0.f;
        split2(v, g_w4h[idx], g_w4l[idx]);
    } else if (bid < NBLK_W1 + NBLK_W4 + NBLK_V) {
        int i = (bid - NBLK_W1 - NBLK_W4) * 256 + tid;
        float4 v = ((const float4*)video)[i];
        __nv_bfloat16 hh[4], ll[4];
        split2(v.x, hh[0], ll[0]);
        split2(v.y, hh[1], ll[1]);
        split2(v.z, hh[2], ll[2]);
        split2(v.w, hh[3], ll[3]);
        *(uint2*)&g_vh[4 * i] = *(uint2*)hh;
        *(uint2*)&g_vl[4 * i] = *(uint2*)ll;
    } else {
        int row = bid - (NBLK_W1 + NBLK_W4 + NBLK_V);
        for (int i = tid; i < DT; i += 256)
            ts[i] = text[row * DT + i];
        __syncthreads();

        float a0 = 0.f, a1 = 0.f, a2 = 0.f, a3 = 0.f;
        const float* w2p = w2 + tid;
        #pragma unroll 5
        for (int d = 0; d < DT; d += 4) {
            a0 += ts[d]     * w2p[(d)     * DA];
            a1 += ts[d + 1] * w2p[(d + 1) * DA];
            a2 += ts[d + 2] * w2p[(d + 2) * DA];
            a3 += ts[d + 3] * w2p[(d + 3) * DA];
        }
        g_f[row * DA + tid] = (a0 + a1) + (a2 + a3);
    }
}

// ---------------------------------------------------------------------------
// Tensor-core GEMM via mma.sync (unchanged from R12 — at legacy-HMMA ceiling).
// CTA tile 128x64, 256 thr / 8 warps, double-buffered smem, 2 CTAs/SM.
// ---------------------------------------------------------------------------
#define PITCH 40
#define OFF_AL (128 * PITCH)
#define OFF_BH (2 * 128 * PITCH)
#define OFF_BL (OFF_BH + 64 * PITCH)
#define SSTG  (OFF_BL + 64 * PITCH)
#define GSMEM (2 * SSTG * (int)sizeof(__nv_bfloat16))   // 61440 B

__global__ void __launch_bounds__(256, 2) k_gemm_mma(
    const __nv_bfloat16* __restrict__ Ah, const __nv_bfloat16* __restrict__ Al,
    const __nv_bfloat16* __restrict__ Bh, const __nv_bfloat16* __restrict__ Bl,
    const float* __restrict__ bias, float* __restrict__ C, int N, int K) {
    extern __shared__ __nv_bfloat16 sm[];

    int tid = threadIdx.x, lane = tid & 31, wid = tid >> 5;
    int g = lane >> 2, tg = lane & 3;
    int brow = blockIdx.x * 128, bn = blockIdx.y * 64;
    int wm = (wid >> 1) * 32, wn = (wid & 1) * 32;

    float acc[2][4][4];
    #pragma unroll
    for (int mi = 0; mi < 2; mi++)
        #pragma unroll
        for (int ni = 0; ni < 4; ni++)
            #pragma unroll
            for (int q = 0; q < 4; q++) acc[mi][ni][q] = 0.f;

    int lrow = tid >> 2;
    int lseg = tid & 3;

    uint4 ra_h[2], ra_l[2], rb_h, rb_l;

    #pragma unroll
    for (int it = 0; it < 2; it++) {
        long ga = (long)(brow + it * 64 + lrow) * K + lseg * 8;
        ra_h[it] = *(const uint4*)&Ah[ga];
        ra_l[it] = *(const uint4*)&Al[ga];
    }
    {
        long gb = (long)(bn + lrow) * K + lseg * 8;
        rb_h = *(const uint4*)&Bh[gb];
        rb_l = *(const uint4*)&Bl[gb];
    }
    #pragma unroll
    for (int it = 0; it < 2; it++) {
        int so = (it * 64 + lrow) * PITCH + lseg * 8;
        *(uint4*)&sm[so] = ra_h[it];
        *(uint4*)&sm[OFF_AL + so] = ra_l[it];
    }
    {
        int so = lrow * PITCH + lseg * 8;
        *(uint4*)&sm[OFF_BH + so] = rb_h;
        *(uint4*)&sm[OFF_BL + so] = rb_l;
    }
    __syncthreads();

    int cur = 0;
    for (int kc = 0; kc < K; kc += 32) {
        bool has_next = (kc + 32 < K);
        if (has_next) {
            #pragma unroll
            for (int it = 0; it < 2; it++) {
                long ga = (long)(brow + it * 64 + lrow) * K + kc + 32 + lseg * 8;
                ra_h[it] = *(const uint4*)&Ah[ga];
                ra_l[it] = *(const uint4*)&Al[ga];
            }
            long gb = (long)(bn + lrow) * K + kc + 32 + lseg * 8;
            rb_h = *(const uint4*)&Bh[gb];
            rb_l = *(const uint4*)&Bl[gb];
        }

        const __nv_bfloat16* sAh = sm + cur * SSTG;
        const __nv_bfloat16* sAl = sAh + OFF_AL;
        const __nv_bfloat16* sBh = sAh + OFF_BH;
        const __nv_bfloat16* sBl = sAh + OFF_BL;

        #pragma unroll
        for (int ks = 0; ks < 2; ks++) {
            int kb = ks * 16 + 2 * tg;
            uint32_t bh0[4], bh1[4], bl0[4], bl1[4];
            #pragma unroll
            for (int ni = 0; ni < 4; ni++) {
                int br = (wn + ni * 8 + g) * PITCH;
                bh0[ni] = *(const uint32_t*)&sBh[br + kb];
                bh1[ni] = *(const uint32_t*)&sBh[br + kb + 8];
                bl0[ni] = *(const uint32_t*)&sBl[br + kb];
                bl1[ni] = *(const uint32_t*)&sBl[br + kb + 8];
            }
            #pragma unroll
            for (int mi = 0; mi < 2; mi++) {
                int ar0 = (wm + mi * 16 + g) * PITCH;
                int ar1 = ar0 + 8 * PITCH;
                uint32_t ah0 = *(const uint32_t*)&sAh[ar0 + kb];
                uint32_t ah1 = *(const uint32_t*)&sAh[ar1 + kb];
                uint32_t ah2 = *(const uint32_t*)&sAh[ar0 + kb + 8];
                uint32_t ah3 = *(const uint32_t*)&sAh[ar1 + kb + 8];
                uint32_t al0 = *(const uint32_t*)&sAl[ar0 + kb];
                uint32_t al1 = *(const uint32_t*)&sAl[ar1 + kb];
                uint32_t al2 = *(const uint32_t*)&sAl[ar0 + kb + 8];
                uint32_t al3 = *(const uint32_t*)&sAl[ar1 + kb + 8];
                #pragma unroll
                for (int ni = 0; ni < 4; ni++)
                    MMA16816(acc[mi][ni], ah0, ah1, ah2, ah3, bh0[ni], bh1[ni]);
                #pragma unroll
                for (int ni = 0; ni < 4; ni++)
                    MMA16816(acc[mi][ni], ah0, ah1, ah2, ah3, bl0[ni], bl1[ni]);
                #pragma unroll
                for (int ni = 0; ni < 4; ni++)
                    MMA16816(acc[mi][ni], al0, al1, al2, al3, bh0[ni], bh1[ni]);
            }
        }

        if (has_next) {
            int nxt = cur ^ 1;
            __nv_bfloat16* d = sm + nxt * SSTG;
            #pragma unroll
            for (int it = 0; it < 2; it++) {
                int so = (it * 64 + lrow) * PITCH + lseg * 8;
                *(uint4*)&d[so] = ra_h[it];
                *(uint4*)&d[OFF_AL + so] = ra_l[it];
            }
            int so = lrow * PITCH + lseg * 8;
            *(uint4*)&d[OFF_BH + so] = rb_h;
            *(uint4*)&d[OFF_BL + so] = rb_l;
            __syncthreads();
            cur = nxt;
        }
    }

    #pragma unroll
    for (int mi = 0; mi < 2; mi++) {
        int row = brow + wm + mi * 16 + g;
        #pragma unroll
        for (int ni = 0; ni < 4; ni++) {
            int col = bn + wn + ni * 8 + 2 * tg;
            if (col < N) {
                float b0 = bias ? bias[col] : 0.f;
                float b1 = bias ? bias[col + 1] : 0.f;
                *(float2*)&C[(long)row * N + col] =
                    make_float2(acc[mi][ni][0] + b0, acc[mi][ni][1] + b1);
                *(float2*)&C[(long)(row + 8) * N + col] =
                    make_float2(acc[mi][ni][2] + b0, acc[mi][ni][3] + b1);
            }
        }
    }
}

// ---------------------------------------------------------------------------
// k_attn: fused attention, restructured.
// - e row loaded straight to registers (ea[8]); ev = ea[warp]. No es smem.
// - w3 hoisted to 8 registers for the block lifetime.
// - sc / inv_s double-buffered by row parity -> only 2 barriers per row.
// - 8 rows per block (grid 1024) for cross-CTA barrier overlap.
// Numerics identical to R12 (same ops, same order).
// ---------------------------------------------------------------------------
#define ROWS_PER_BLK 8

__global__ __launch_bounds__(256) void k_attn(const float* __restrict__ w3,
                                              const float* __restrict__ bias) {
    __shared__ float fb[S2 * DA];
    __shared__ float bs[DA];
    __shared__ float sc[2][S2];
    __shared__ float inv_s[2];

    int tid = threadIdx.x;
    int b = blockIdx.x, s0 = blockIdx.y * ROWS_PER_BLK;
    int warp = tid >> 5, lane = tid & 31;

    bs[tid] = bias[tid];
    float bs_t = bias[tid];
    float w3r[8];
    #pragma unroll
    for (int j = 0; j < 8; j++) w3r[j] = w3[lane + 32 * j];
    __syncthreads();                       // bs visible for fb fill
    for (int i = tid; i < S2 * DA; i += 256)
        fb[i] = g_f[b * S2 * DA + i] + bs[i & (DA - 1)];
    __syncthreads();                       // fb ready

    for (int r = 0; r < ROWS_PER_BLK; r++) {
        int s = s0 + r;
        int pr = r & 1;
        long erow = ((long)b * S1 + s) * DA;

        // e row -> registers (coalesced per j; L2-resident)
        float ea[8];
        #pragma unroll
        for (int j = 0; j < 8; j++) ea[j] = g_e[erow + lane + 32 * j];

        // stage 1: logits
        #pragma unroll
        for (int tt = 0; tt < 5; tt++) {
            int t = warp + 8 * tt;
            float p = 0.f;
            #pragma unroll
            for (int j = 0; j < 8; j++)
                p += fast_tanh(ea[j] + fb[t * DA + lane + 32 * j]) * w3r[j];
            #pragma unroll
            for (int off = 16; off; off >>= 1)
                p += __shfl_xor_sync(0xffffffffu, p, off);
            if (lane == 0) sc[pr][t] = p;
        }
        __syncthreads();                   // B1: logits complete

        // stage 2: softmax stats in warp 0
        if (warp == 0) {
            float v0 = sc[pr][lane];
            float v1 = (lane + 32 < S2) ? sc[pr][lane + 32] : -3.4e38f;
            float m = fmaxf(v0, v1);
            #pragma unroll
            for (int off = 16; off; off >>= 1)
                m = fmaxf(m, __shfl_xor_sync(0xffffffffu, m, off));
            float e0 = __expf(v0 - m);
            float e1 = (lane + 32 < S2) ? __expf(v1 - m) : 0.f;
            float su = e0 + e1;
            #pragma unroll
            for (int off = 16; off; off >>= 1)
                su += __shfl_xor_sync(0xffffffffu, su, off);
            sc[pr][lane] = e0;
            if (lane + 32 < S2) sc[pr][lane + 32] = e1;
            if (lane == 0) inv_s[pr] = 1.f / su;
        }
        __syncthreads();                   // B2: weights ready

        // stage 3+4: text_attn + features -> split bf16
        float acc = 0.f;
        #pragma unroll 8
        for (int t = 0; t < S2; t++)
            acc += sc[pr][t] * fb[t * DA + tid];
        float ta = acc * inv_s[pr] - bs_t;
        float ev = ea[warp];

        long go = ((long)b * S1 + s) * (4 * DA) + tid;
        float vals[4] = {fast_tanh(ev), fast_tanh(ta),
                         fast_tanh(ev * ta), fast_tanh(ev - ta)};
        #pragma unroll
        for (int q = 0; q < 4; q++) {
            __nv_bfloat16 h = __float2bfloat16(vals[q]);
            g_gh[go + q * DA] = h;
            g_gl[go + q * DA] = __float2bfloat16(vals[q] - __bfloat162float(h));
        }
        // no trailing barrier: next row uses sc[pr^1]; reuse of sc[pr] is
        // fenced by B1 of the next row (all warps past stage3 by then).
    }
}

// ---------------------------------------------------------------------------
extern "C" void kernel_launch(void* const* d_in, const int* in_sizes, int n_in,
                              void* d_out, int out_size) {
    const float* video = (const float*)d_in[0];
    const float* text  = (const float*)d_in[1];
    const float* w1    = (const float*)d_in[2];
    const float* w2    = (const float*)d_in[3];
    const float* w3    = (const float*)d_in[4];
    const float* bias  = (const float*)d_in[5];
    const float* w4    = (const float*)d_in[6];
    const float* b4    = (const float*)d_in[7];
    float* out = (float*)d_out;

    float* pe;
    __nv_bfloat16 *pvh, *pvl, *pgh, *pgl, *p1h, *p1l, *p4h, *p4l;
    cudaGetSymbolAddress((void**)&pe, g_e);
    cudaGetSymbolAddress((void**)&pvh, g_vh);
    cudaGetSymbolAddress((void**)&pvl, g_vl);
    cudaGetSymbolAddress((void**)&pgh, g_gh);
    cudaGetSymbolAddress((void**)&pgl, g_gl);
    cudaGetSymbolAddress((void**)&p1h, g_w1h);
    cudaGetSymbolAddress((void**)&p1l, g_w1l);
    cudaGetSymbolAddress((void**)&p4h, g_w4h);
    cudaGetSymbolAddress((void**)&p4l, g_w4l);

    cudaFuncSetAttribute(k_gemm_mma, cudaFuncAttributeMaxDynamicSharedMemorySize,
                         GSMEM);

    // fused prologue
    k_pre<<<NBLK_W1 + NBLK_W4 + NBLK_V + NBLK_T, 256>>>(w1, w4, video, text, w2);
    // e = video @ w1  (8192x256, K=1024)
    k_gemm_mma<<<dim3((NB * S1) / 128, DA / 64), 256, GSMEM>>>(
        pvh, pvl, p1h, p1l, nullptr, pe, DA, DV);
    // fused attention -> g (split bf16)
    k_attn<<<dim3(NB, S1 / ROWS_PER_BLK), 256>>>(w3, bias);
    // out = g @ w4 + b4  (8192x500, K=1024)
    k_gemm_mma<<<dim3((NB * S1) / 128, DO_PAD / 64), 256, GSMEM>>>(
        pgh, pgl, p4h, p4l, b4, out, DO, 4 * DA);
}

// round 14
// speedup vs baseline: 1.1343x; 1.0820x over previous
#include <cuda_runtime.h>
#include <cuda_bf16.h>
#include <math.h>
#include <cstdint>

#define NB 16
#define S1 512
#define S2 40
#define DV 1024
#define DT 300
#define DA 256
#define DO 500
#define DO_PAD 512

// ---------------------------------------------------------------------------
// Scratch (static device globals: allocation-free)
// ---------------------------------------------------------------------------
__device__ float g_f[NB * S2 * DA];                    // f = text @ w2    (16,40,256)
__device__ float g_e[NB * S1 * DA];                    // e = video @ w1   (16,512,256)
__device__ __nv_bfloat16 g_vh[NB * S1 * DV];           // video split hi
__device__ __nv_bfloat16 g_vl[NB * S1 * DV];           // video split lo
__device__ __nv_bfloat16 g_gh[NB * S1 * 4 * DA];       // tanh(cont) split hi
__device__ __nv_bfloat16 g_gl[NB * S1 * 4 * DA];       // tanh(cont) split lo
__device__ __nv_bfloat16 g_w1h[DA * DV];               // w1^T hi [256,1024]
__device__ __nv_bfloat16 g_w1l[DA * DV];               // w1^T lo
__device__ __nv_bfloat16 g_w4h[DO_PAD * (4 * DA)];     // w4^T hi [512,1024] (rows>=500 zero)
__device__ __nv_bfloat16 g_w4l[DO_PAD * (4 * DA)];     // w4^T lo

// ---------------------------------------------------------------------------
// Fast accurate tanh: 2 MUFU + ~5 ALU, rel err ~1e-6
// ---------------------------------------------------------------------------
__device__ __forceinline__ float fast_tanh(float x) {
    float ax = fabsf(x);
    float e = __expf(-2.f * ax);
    float t = __fdividef(1.f - e, 1.f + e);
    return copysignf(t, x);
}

// mma.sync m16n8k16 bf16 (sm_80+ base feature)
#define MMA16816(c, a0, a1, a2, a3, b0, b1)                                  \
    asm volatile(                                                            \
        "mma.sync.aligned.m16n8k16.row.col.f32.bf16.bf16.f32 "               \
        "{%0,%1,%2,%3}, {%4,%5,%6,%7}, {%8,%9}, {%0,%1,%2,%3};"              \
        : "+f"((c)[0]), "+f"((c)[1]), "+f"((c)[2]), "+f"((c)[3])             \
        : "r"(a0), "r"(a1), "r"(a2), "r"(a3), "r"(b0), "r"(b1))

// ldmatrix x4 (sm_75+ base feature)
#define LDSM_X4(r0, r1, r2, r3, addr)                                        \
    asm volatile(                                                            \
        "ldmatrix.sync.aligned.m8n8.x4.shared.b16 {%0,%1,%2,%3}, [%4];"      \
        : "=r"(r0), "=r"(r1), "=r"(r2), "=r"(r3) : "r"(addr))

__device__ __forceinline__ void split2(float v, __nv_bfloat16& h, __nv_bfloat16& l) {
    h = __float2bfloat16(v);
    l = __float2bfloat16(v - __bfloat162float(h));
}

// ---------------------------------------------------------------------------
// k_pre: fused prologue — one launch, four independent jobs by block range.
// ---------------------------------------------------------------------------
#define NBLK_W1 ((DA * DV) / 256)               // 1024
#define NBLK_W4 ((DO_PAD * 4 * DA) / 256)       // 2048
#define NBLK_V  ((NB * S1 * DV / 4) / 256)      // 8192
#define NBLK_T  (NB * S2)                       // 640

__global__ __launch_bounds__(256) void k_pre(const float* __restrict__ w1,
                                             const float* __restrict__ w4,
                                             const float* __restrict__ video,
                                             const float* __restrict__ text,
                                             const float* __restrict__ w2) {
    __shared__ float ts[DT];
    int bid = blockIdx.x, tid = threadIdx.x;

    if (bid < NBLK_W1) {
        int idx = bid * 256 + tid;
        int n = idx >> 10, k = idx & (DV - 1);
        float v = w1[(long)k * DA + n];
        split2(v, g_w1h[idx], g_w1l[idx]);
    } else if (bid < NBLK_W1 + NBLK_W4) {
        int idx = (bid - NBLK_W1) * 256 + tid;
        int n = idx >> 10, k = idx & (4 * DA - 1);
        float v = (n < DO) ? w4[(long)k * DO + n] : 0.f;
        split2(v, g_w4h[idx], g_w4l[idx]);
    } else if (bid < NBLK_W1 + NBLK_W4 + NBLK_V) {
        int i = (bid - NBLK_W1 - NBLK_W4) * 256 + tid;
        float4 v = ((const float4*)video)[i];
        __nv_bfloat16 hh[4], ll[4];
        split2(v.x, hh[0], ll[0]);
        split2(v.y, hh[1], ll[1]);
        split2(v.z, hh[2], ll[2]);
        split2(v.w, hh[3], ll[3]);
        *(uint2*)&g_vh[4 * i] = *(uint2*)hh;
        *(uint2*)&g_vl[4 * i] = *(uint2*)ll;
    } else {
        int row = bid - (NBLK_W1 + NBLK_W4 + NBLK_V);
        for (int i = tid; i < DT; i += 256)
            ts[i] = text[row * DT + i];
        __syncthreads();

        float a0 = 0.f, a1 = 0.f, a2 = 0.f, a3 = 0.f;
        const float* w2p = w2 + tid;
        #pragma unroll 5
        for (int d = 0; d < DT; d += 4) {
            a0 += ts[d]     * w2p[(d)     * DA];
            a1 += ts[d + 1] * w2p[(d + 1) * DA];
            a2 += ts[d + 2] * w2p[(d + 2) * DA];
            a3 += ts[d + 3] * w2p[(d + 3) * DA];
        }
        g_f[row * DA + tid] = (a0 + a1) + (a2 + a3);
    }
}

// ---------------------------------------------------------------------------
// Tensor-core GEMM via mma.sync + ldmatrix: C = A @ Bt^T (+bias), split-bf16.
// CTA tile 128x64, 256 thr / 8 warps 4(M)x2(N), warp 32x32, double-buffered
// smem, 2 CTAs/SM. Fragment loads via ldmatrix.x4: 16 loads/chunk/warp
// (was 64 scalar LDS).
// ---------------------------------------------------------------------------
#define PITCH 40
#define OFF_AL (128 * PITCH)
#define OFF_BH (2 * 128 * PITCH)
#define OFF_BL (OFF_BH + 64 * PITCH)
#define SSTG  (OFF_BL + 64 * PITCH)
#define GSMEM (2 * SSTG * (int)sizeof(__nv_bfloat16))   // 61440 B

__global__ void __launch_bounds__(256, 2) k_gemm_mma(
    const __nv_bfloat16* __restrict__ Ah, const __nv_bfloat16* __restrict__ Al,
    const __nv_bfloat16* __restrict__ Bh, const __nv_bfloat16* __restrict__ Bl,
    const float* __restrict__ bias, float* __restrict__ C, int N, int K) {
    extern __shared__ __nv_bfloat16 sm[];

    int tid = threadIdx.x, lane = tid & 31, wid = tid >> 5;
    int g = lane >> 2, tg = lane & 3;
    int brow = blockIdx.x * 128, bn = blockIdx.y * 64;
    int wm = (wid >> 1) * 32, wn = (wid & 1) * 32;

    float acc[2][4][4];
    #pragma unroll
    for (int mi = 0; mi < 2; mi++)
        #pragma unroll
        for (int ni = 0; ni < 4; ni++)
            #pragma unroll
            for (int q = 0; q < 4; q++) acc[mi][ni][q] = 0.f;

    int lrow = tid >> 2;
    int lseg = tid & 3;

    // ldmatrix per-lane byte offsets (within a stage, in bytes)
    // A tiles: t=lane>>3: row += (t&1)*8, col += (t>>1)*8
    uint32_t smem_u32 = (uint32_t)__cvta_generic_to_shared(sm);
    int aRow = wm + ((lane >> 3) & 1) * 8 + (lane & 7);
    int aCol = ((lane >> 4) & 1) * 8;
    uint32_t aOff = (uint32_t)(aRow * PITCH + aCol) * 2;
    // B tiles: t=lane>>3: row += (t>>1)*8, col += (t&1)*8
    int bRow = wn + ((lane >> 4) & 1) * 8 + (lane & 7);
    int bCol = ((lane >> 3) & 1) * 8;
    uint32_t bOff = (uint32_t)(bRow * PITCH + bCol) * 2;

    uint4 ra_h[2], ra_l[2], rb_h, rb_l;

    #pragma unroll
    for (int it = 0; it < 2; it++) {
        long ga = (long)(brow + it * 64 + lrow) * K + lseg * 8;
        ra_h[it] = *(const uint4*)&Ah[ga];
        ra_l[it] = *(const uint4*)&Al[ga];
    }
    {
        long gb = (long)(bn + lrow) * K + lseg * 8;
        rb_h = *(const uint4*)&Bh[gb];
        rb_l = *(const uint4*)&Bl[gb];
    }
    #pragma unroll
    for (int it = 0; it < 2; it++) {
        int so = (it * 64 + lrow) * PITCH + lseg * 8;
        *(uint4*)&sm[so] = ra_h[it];
        *(uint4*)&sm[OFF_AL + so] = ra_l[it];
    }
    {
        int so = lrow * PITCH + lseg * 8;
        *(uint4*)&sm[OFF_BH + so] = rb_h;
        *(uint4*)&sm[OFF_BL + so] = rb_l;
    }
    __syncthreads();

    int cur = 0;
    for (int kc = 0; kc < K; kc += 32) {
        bool has_next = (kc + 32 < K);
        if (has_next) {
            #pragma unroll
            for (int it = 0; it < 2; it++) {
                long ga = (long)(brow + it * 64 + lrow) * K + kc + 32 + lseg * 8;
                ra_h[it] = *(const uint4*)&Ah[ga];
                ra_l[it] = *(const uint4*)&Al[ga];
            }
            long gb = (long)(bn + lrow) * K + kc + 32 + lseg * 8;
            rb_h = *(const uint4*)&Bh[gb];
            rb_l = *(const uint4*)&Bl[gb];
        }

        uint32_t stgAH = smem_u32 + (uint32_t)(cur * SSTG) * 2;
        uint32_t stgAL = stgAH + OFF_AL * 2;
        uint32_t stgBH = stgAH + OFF_BH * 2;
        uint32_t stgBL = stgAH + OFF_BL * 2;

        #pragma unroll
        for (int ks = 0; ks < 2; ks++) {
            uint32_t kof = (uint32_t)(ks * 32);   // 16 bf16 = 32 bytes
            // B fragments: per ni-pair p, x4 gives (b0,b1) for ni=2p and 2p+1
            uint32_t bhf[2][4], blf[2][4];
            #pragma unroll
            for (int p = 0; p < 2; p++) {
                uint32_t ba = bOff + (uint32_t)(p * 16 * PITCH) * 2 + kof;
                LDSM_X4(bhf[p][0], bhf[p][1], bhf[p][2], bhf[p][3], stgBH + ba);
                LDSM_X4(blf[p][0], blf[p][1], blf[p][2], blf[p][3], stgBL + ba);
            }
            #pragma unroll
            for (int mi = 0; mi < 2; mi++) {
                uint32_t aa = aOff + (uint32_t)(mi * 16 * PITCH) * 2 + kof;
                uint32_t ah[4], al[4];
                LDSM_X4(ah[0], ah[1], ah[2], ah[3], stgAH + aa);
                LDSM_X4(al[0], al[1], al[2], al[3], stgAL + aa);
                // product sweeps: consecutive MMAs hit different accumulators
                #pragma unroll
                for (int ni = 0; ni < 4; ni++)
                    MMA16816(acc[mi][ni], ah[0], ah[1], ah[2], ah[3],
                             bhf[ni >> 1][(ni & 1) * 2], bhf[ni >> 1][(ni & 1) * 2 + 1]);
                #pragma unroll
                for (int ni = 0; ni < 4; ni++)
                    MMA16816(acc[mi][ni], ah[0], ah[1], ah[2], ah[3],
                             blf[ni >> 1][(ni & 1) * 2], blf[ni >> 1][(ni & 1) * 2 + 1]);
                #pragma unroll
                for (int ni = 0; ni < 4; ni++)
                    MMA16816(acc[mi][ni], al[0], al[1], al[2], al[3],
                             bhf[ni >> 1][(ni & 1) * 2], bhf[ni >> 1][(ni & 1) * 2 + 1]);
            }
        }

        if (has_next) {
            int nxt = cur ^ 1;
            __nv_bfloat16* d = sm + nxt * SSTG;
            #pragma unroll
            for (int it = 0; it < 2; it++) {
                int so = (it * 64 + lrow) * PITCH + lseg * 8;
                *(uint4*)&d[so] = ra_h[it];
                *(uint4*)&d[OFF_AL + so] = ra_l[it];
            }
            int so = lrow * PITCH + lseg * 8;
            *(uint4*)&d[OFF_BH + so] = rb_h;
            *(uint4*)&d[OFF_BL + so] = rb_l;
            __syncthreads();
            cur = nxt;
        }
    }

    #pragma unroll
    for (int mi = 0; mi < 2; mi++) {
        int row = brow + wm + mi * 16 + g;
        #pragma unroll
        for (int ni = 0; ni < 4; ni++) {
            int col = bn + wn + ni * 8 + 2 * tg;
            if (col < N) {
                float b0 = bias ? bias[col] : 0.f;
                float b1 = bias ? bias[col + 1] : 0.f;
                *(float2*)&C[(long)row * N + col] =
                    make_float2(acc[mi][ni][0] + b0, acc[mi][ni][1] + b1);
                *(float2*)&C[(long)(row + 8) * N + col] =
                    make_float2(acc[mi][ni][2] + b0, acc[mi][ni][3] + b1);
            }
        }
    }
}

// ---------------------------------------------------------------------------
// k_attn: fused attention (unchanged from R13).
// ---------------------------------------------------------------------------
#define ROWS_PER_BLK 8

__global__ __launch_bounds__(256) void k_attn(const float* __restrict__ w3,
                                              const float* __restrict__ bias) {
    __shared__ float fb[S2 * DA];
    __shared__ float bs[DA];
    __shared__ float sc[2][S2];
    __shared__ float inv_s[2];

    int tid = threadIdx.x;
    int b = blockIdx.x, s0 = blockIdx.y * ROWS_PER_BLK;
    int warp = tid >> 5, lane = tid & 31;

    bs[tid] = bias[tid];
    float bs_t = bias[tid];
    float w3r[8];
    #pragma unroll
    for (int j = 0; j < 8; j++) w3r[j] = w3[lane + 32 * j];
    __syncthreads();
    for (int i = tid; i < S2 * DA; i += 256)
        fb[i] = g_f[b * S2 * DA + i] + bs[i & (DA - 1)];
    __syncthreads();

    for (int r = 0; r < ROWS_PER_BLK; r++) {
        int s = s0 + r;
        int pr = r & 1;
        long erow = ((long)b * S1 + s) * DA;

        float ea[8];
        #pragma unroll
        for (int j = 0; j < 8; j++) ea[j] = g_e[erow + lane + 32 * j];

        #pragma unroll
        for (int tt = 0; tt < 5; tt++) {
            int t = warp + 8 * tt;
            float p = 0.f;
            #pragma unroll
            for (int j = 0; j < 8; j++)
                p += fast_tanh(ea[j] + fb[t * DA + lane + 32 * j]) * w3r[j];
            #pragma unroll
            for (int off = 16; off; off >>= 1)
                p += __shfl_xor_sync(0xffffffffu, p, off);
            if (lane == 0) sc[pr][t] = p;
        }
        __syncthreads();

        if (warp == 0) {
            float v0 = sc[pr][lane];
            float v1 = (lane + 32 < S2) ? sc[pr][lane + 32] : -3.4e38f;
            float m = fmaxf(v0, v1);
            #pragma unroll
            for (int off = 16; off; off >>= 1)
                m = fmaxf(m, __shfl_xor_sync(0xffffffffu, m, off));
            float e0 = __expf(v0 - m);
            float e1 = (lane + 32 < S2) ? __expf(v1 - m) : 0.f;
            float su = e0 + e1;
            #pragma unroll
            for (int off = 16; off; off >>= 1)
                su += __shfl_xor_sync(0xffffffffu, su, off);
            sc[pr][lane] = e0;
            if (lane + 32 < S2) sc[pr][lane + 32] = e1;
            if (lane == 0) inv_s[pr] = 1.f / su;
        }
        __syncthreads();

        float acc = 0.f;
        #pragma unroll 8
        for (int t = 0; t < S2; t++)
            acc += sc[pr][t] * fb[t * DA + tid];
        float ta = acc * inv_s[pr] - bs_t;
        float ev = ea[warp];

        long go = ((long)b * S1 + s) * (4 * DA) + tid;
        float vals[4] = {fast_tanh(ev), fast_tanh(ta),
                         fast_tanh(ev * ta), fast_tanh(ev - ta)};
        #pragma unroll
        for (int q = 0; q < 4; q++) {
            __nv_bfloat16 h = __float2bfloat16(vals[q]);
            g_gh[go + q * DA] = h;
            g_gl[go + q * DA] = __float2bfloat16(vals[q] - __bfloat162float(h));
        }
    }
}

// ---------------------------------------------------------------------------
extern "C" void kernel_launch(void* const* d_in, const int* in_sizes, int n_in,
                              void* d_out, int out_size) {
    const float* video = (const float*)d_in[0];
    const float* text  = (const float*)d_in[1];
    const float* w1    = (const float*)d_in[2];
    const float* w2    = (const float*)d_in[3];
    const float* w3    = (const float*)d_in[4];
    const float* bias  = (const float*)d_in[5];
    const float* w4    = (const float*)d_in[6];
    const float* b4    = (const float*)d_in[7];
    float* out = (float*)d_out;

    float* pe;
    __nv_bfloat16 *pvh, *pvl, *pgh, *pgl, *p1h, *p1l, *p4h, *p4l;
    cudaGetSymbolAddress((void**)&pe, g_e);
    cudaGetSymbolAddress((void**)&pvh, g_vh);
    cudaGetSymbolAddress((void**)&pvl, g_vl);
    cudaGetSymbolAddress((void**)&pgh, g_gh);
    cudaGetSymbolAddress((void**)&pgl, g_gl);
    cudaGetSymbolAddress((void**)&p1h, g_w1h);
    cudaGetSymbolAddress((void**)&p1l, g_w1l);
    cudaGetSymbolAddress((void**)&p4h, g_w4h);
    cudaGetSymbolAddress((void**)&p4l, g_w4l);

    cudaFuncSetAttribute(k_gemm_mma, cudaFuncAttributeMaxDynamicSharedMemorySize,
                         GSMEM);

    // fused prologue
    k_pre<<<NBLK_W1 + NBLK_W4 + NBLK_V + NBLK_T, 256>>>(w1, w4, video, text, w2);
    // e = video @ w1  (8192x256, K=1024)
    k_gemm_mma<<<dim3((NB * S1) / 128, DA / 64), 256, GSMEM>>>(
        pvh, pvl, p1h, p1l, nullptr, pe, DA, DV);
    // fused attention -> g (split bf16)
    k_attn<<<dim3(NB, S1 / ROWS_PER_BLK), 256>>>(w3, bias);
    // out = g @ w4 + b4  (8192x500, K=1024)
    k_gemm_mma<<<dim3((NB * S1) / 128, DO_PAD / 64), 256, GSMEM>>>(
        pgh, pgl, p4h, p4l, b4, out, DO, 4 * DA);
}

// round 17
// speedup vs baseline: 1.1429x; 1.0076x over previous
#include <cuda_runtime.h>
#include <cuda_bf16.h>
#include <math.h>
#include <cstdint>

#define NB 16
#define S1 512
#define S2 40
#define DV 1024
#define DT 300
#define DA 256
#define DO 500
#define DO_PAD 512

// ---------------------------------------------------------------------------
// Scratch (static device globals: allocation-free)
// ---------------------------------------------------------------------------
__device__ float g_f[NB * S2 * DA];                    // f = text @ w2    (16,40,256)
__device__ float g_e[NB * S1 * DA];                    // e = video @ w1   (16,512,256)
__device__ __nv_bfloat16 g_vh[NB * S1 * DV];           // video split hi
__device__ __nv_bfloat16 g_vl[NB * S1 * DV];           // video split lo
__device__ __nv_bfloat16 g_gh[NB * S1 * 4 * DA];       // tanh(cont) split hi
__device__ __nv_bfloat16 g_gl[NB * S1 * 4 * DA];       // tanh(cont) split lo
__device__ __nv_bfloat16 g_w1h[DA * DV];               // w1^T hi [256,1024]
__device__ __nv_bfloat16 g_w1l[DA * DV];               // w1^T lo
__device__ __nv_bfloat16 g_w4h[DO_PAD * (4 * DA)];     // w4^T hi [512,1024] (rows>=500 zero)
__device__ __nv_bfloat16 g_w4l[DO_PAD * (4 * DA)];     // w4^T lo

// ---------------------------------------------------------------------------
// Fast accurate tanh: 2 MUFU + ~5 ALU, rel err ~1e-6
// ---------------------------------------------------------------------------
__device__ __forceinline__ float fast_tanh(float x) {
    float ax = fabsf(x);
    float e = __expf(-2.f * ax);
    float t = __fdividef(1.f - e, 1.f + e);
    return copysignf(t, x);
}

// mma.sync m16n8k16 bf16 (sm_80+ base feature)
#define MMA16816(c, a0, a1, a2, a3, b0, b1)                                  \
    asm volatile(                                                            \
        "mma.sync.aligned.m16n8k16.row.col.f32.bf16.bf16.f32 "               \
        "{%0,%1,%2,%3}, {%4,%5,%6,%7}, {%8,%9}, {%0,%1,%2,%3};"              \
        : "+f"((c)[0]), "+f"((c)[1]), "+f"((c)[2]), "+f"((c)[3])             \
        : "r"(a0), "r"(a1), "r"(a2), "r"(a3), "r"(b0), "r"(b1))

// ldmatrix x4 (sm_75+ base feature)
#define LDSM_X4(r0, r1, r2, r3, addr)                                        \
    asm volatile(                                                            \
        "ldmatrix.sync.aligned.m8n8.x4.shared.b16 {%0,%1,%2,%3}, [%4];"      \
        : "=r"(r0), "=r"(r1), "=r"(r2), "=r"(r3) : "r"(addr))

__device__ __forceinline__ void split2(float v, __nv_bfloat16& h, __nv_bfloat16& l) {
    h = __float2bfloat16(v);
    l = __float2bfloat16(v - __bfloat162float(h));
}

// ---------------------------------------------------------------------------
// k_pre: fused prologue — one launch, four independent jobs by block range.
//   [0, 256)        : w1^T split prep — 32x32 smem-tile transpose (coalesced)
//   [256, 768)      : w4^T split prep — same, rows >= 500 zeroed
//   [768, 8960)     : video fp32 -> hi/lo bf16 split (float4 per thread)
//   [8960, 9600)    : text_proj, one (b,t) row per block, 4 accumulators
// ---------------------------------------------------------------------------
#define NBLK_W1T ((DA / 32) * (DV / 32))              // 256
#define NBLK_W4T ((DO_PAD / 32) * ((4 * DA) / 32))    // 512
#define NBLK_V   ((NB * S1 * DV / 4) / 256)           // 8192
#define NBLK_T   (NB * S2)                            // 640

__global__ __launch_bounds__(256) void k_pre(const float* __restrict__ w1,
                                             const float* __restrict__ w4,
                                             const float* __restrict__ video,
                                             const float* __restrict__ text,
                                             const float* __restrict__ w2) {
    __shared__ float sbuf[32 * 33];   // transpose tile; reused as ts[] by text job
    int bid = blockIdx.x, tid = threadIdx.x;

    if (bid < NBLK_W1T + NBLK_W4T) {
        // coalesced weight transpose + split via 32x32 smem tile
        bool isw1 = bid < NBLK_W1T;
        int t = isw1 ? bid : bid - NBLK_W1T;
        int ntn = isw1 ? (DA / 32) : (DO_PAD / 32);
        int n0 = (t % ntn) * 32;
        int k0 = (t / ntn) * 32;
        int Nsrc = isw1 ? DA : DO;
        int Kd = isw1 ? DV : 4 * DA;
        const float* W = isw1 ? w1 : w4;
        __nv_bfloat16* Oh = isw1 ? g_w1h : g_w4h;
        __nv_bfloat16* Ol = isw1 ? g_w1l : g_w4l;

        int ty = tid >> 5, tx = tid & 31;
        #pragma unroll
        for (int i = 0; i < 4; i++) {
            int k = k0 + ty + i * 8;
            int n = n0 + tx;
            float v = (n < Nsrc) ? W[(long)k * Nsrc + n] : 0.f;   // coalesced in n
            sbuf[(ty + i * 8) * 33 + tx] = v;
        }
        __syncthreads();
        #pragma unroll
        for (int i = 0; i < 4; i++) {
            int n = n0 + ty + i * 8;
            int k = k0 + tx;
            float v = sbuf[tx * 33 + ty + i * 8];
            __nv_bfloat16 h, l;
            split2(v, h, l);
            long o = (long)n * Kd + k;                            // coalesced in k
            Oh[o] = h;
            Ol[o] = l;
        }
    } else if (bid < NBLK_W1T + NBLK_W4T + NBLK_V) {
        int i = (bid - NBLK_W1T - NBLK_W4T) * 256 + tid;
        float4 v = ((const float4*)video)[i];
        __nv_bfloat16 hh[4], ll[4];
        split2(v.x, hh[0], ll[0]);
        split2(v.y, hh[1], ll[1]);
        split2(v.z, hh[2], ll[2]);
        split2(v.w, hh[3], ll[3]);
        *(uint2*)&g_vh[4 * i] = *(uint2*)hh;
        *(uint2*)&g_vl[4 * i] = *(uint2*)ll;
    } else {
        int row = bid - (NBLK_W1T + NBLK_W4T + NBLK_V);
        float* ts = sbuf;                                         // 300 <= 1056
        for (int i = tid; i < DT; i += 256)
            ts[i] = text[row * DT + i];
        __syncthreads();

        float a0 = 0.f, a1 = 0.f, a2 = 0.f, a3 = 0.f;
        const float* w2p = w2 + tid;
        #pragma unroll 5
        for (int d = 0; d < DT; d += 4) {
            a0 += ts[d]     * w2p[(d)     * DA];
            a1 += ts[d + 1] * w2p[(d + 1) * DA];
            a2 += ts[d + 2] * w2p[(d + 2) * DA];
            a3 += ts[d + 3] * w2p[(d + 3) * DA];
        }
        g_f[row * DA + tid] = (a0 + a1) + (a2 + a3);
    }
}

// ---------------------------------------------------------------------------
// Tensor-core GEMM via mma.sync + ldmatrix (EXACT R14 kernel — last-good).
// CTA tile 128x64, 256 thr / 8 warps 4(M)x2(N), warp 32x32, double-buffered
// smem, 2 CTAs/SM.
// ---------------------------------------------------------------------------
#define PITCH 40
#define OFF_AL (128 * PITCH)
#define OFF_BH (2 * 128 * PITCH)
#define OFF_BL (OFF_BH + 64 * PITCH)
#define SSTG  (OFF_BL + 64 * PITCH)
#define GSMEM (2 * SSTG * (int)sizeof(__nv_bfloat16))   // 61440 B

__global__ void __launch_bounds__(256, 2) k_gemm_mma(
    const __nv_bfloat16* __restrict__ Ah, const __nv_bfloat16* __restrict__ Al,
    const __nv_bfloat16* __restrict__ Bh, const __nv_bfloat16* __restrict__ Bl,
    const float* __restrict__ bias, float* __restrict__ C, int N, int K) {
    extern __shared__ __nv_bfloat16 sm[];

    int tid = threadIdx.x, lane = tid & 31, wid = tid >> 5;
    int g = lane >> 2, tg = lane & 3;
    int brow = blockIdx.x * 128, bn = blockIdx.y * 64;
    int wm = (wid >> 1) * 32, wn = (wid & 1) * 32;

    float acc[2][4][4];
    #pragma unroll
    for (int mi = 0; mi < 2; mi++)
        #pragma unroll
        for (int ni = 0; ni < 4; ni++)
            #pragma unroll
            for (int q = 0; q < 4; q++) acc[mi][ni][q] = 0.f;

    int lrow = tid >> 2;
    int lseg = tid & 3;

    uint32_t smem_u32 = (uint32_t)__cvta_generic_to_shared(sm);
    int aRow = wm + ((lane >> 3) & 1) * 8 + (lane & 7);
    int aCol = ((lane >> 4) & 1) * 8;
    uint32_t aOff = (uint32_t)(aRow * PITCH + aCol) * 2;
    int bRow = wn + ((lane >> 4) & 1) * 8 + (lane & 7);
    int bCol = ((lane >> 3) & 1) * 8;
    uint32_t bOff = (uint32_t)(bRow * PITCH + bCol) * 2;

    uint4 ra_h[2], ra_l[2], rb_h, rb_l;

    #pragma unroll
    for (int it = 0; it < 2; it++) {
        long ga = (long)(brow + it * 64 + lrow) * K + lseg * 8;
        ra_h[it] = *(const uint4*)&Ah[ga];
        ra_l[it] = *(const uint4*)&Al[ga];
    }
    {
        long gb = (long)(bn + lrow) * K + lseg * 8;
        rb_h = *(const uint4*)&Bh[gb];
        rb_l = *(const uint4*)&Bl[gb];
    }
    #pragma unroll
    for (int it = 0; it < 2; it++) {
        int so = (it * 64 + lrow) * PITCH + lseg * 8;
        *(uint4*)&sm[so] = ra_h[it];
        *(uint4*)&sm[OFF_AL + so] = ra_l[it];
    }
    {
        int so = lrow * PITCH + lseg * 8;
        *(uint4*)&sm[OFF_BH + so] = rb_h;
        *(uint4*)&sm[OFF_BL + so] = rb_l;
    }
    __syncthreads();

    int cur = 0;
    for (int kc = 0; kc < K; kc += 32) {
        bool has_next = (kc + 32 < K);
        if (has_next) {
            #pragma unroll
            for (int it = 0; it < 2; it++) {
                long ga = (long)(brow + it * 64 + lrow) * K + kc + 32 + lseg * 8;
                ra_h[it] = *(const uint4*)&Ah[ga];
                ra_l[it] = *(const uint4*)&Al[ga];
            }
            long gb = (long)(bn + lrow) * K + kc + 32 + lseg * 8;
            rb_h = *(const uint4*)&Bh[gb];
            rb_l = *(const uint4*)&Bl[gb];
        }

        uint32_t stgAH = smem_u32 + (uint32_t)(cur * SSTG) * 2;
        uint32_t stgAL = stgAH + OFF_AL * 2;
        uint32_t stgBH = stgAH + OFF_BH * 2;
        uint32_t stgBL = stgAH + OFF_BL * 2;

        #pragma unroll
        for (int ks = 0; ks < 2; ks++) {
            uint32_t kof = (uint32_t)(ks * 32);   // 16 bf16 = 32 bytes
            uint32_t bhf[2][4], blf[2][4];
            #pragma unroll
            for (int p = 0; p < 2; p++) {
                uint32_t ba = bOff + (uint32_t)(p * 16 * PITCH) * 2 + kof;
                LDSM_X4(bhf[p][0], bhf[p][1], bhf[p][2], bhf[p][3], stgBH + ba);
                LDSM_X4(blf[p][0], blf[p][1], blf[p][2], blf[p][3], stgBL + ba);
            }
            #pragma unroll
            for (int mi = 0; mi < 2; mi++) {
                uint32_t aa = aOff + (uint32_t)(mi * 16 * PITCH) * 2 + kof;
                uint32_t ah[4], al[4];
                LDSM_X4(ah[0], ah[1], ah[2], ah[3], stgAH + aa);
                LDSM_X4(al[0], al[1], al[2], al[3], stgAL + aa);
                #pragma unroll
                for (int ni = 0; ni < 4; ni++)
                    MMA16816(acc[mi][ni], ah[0], ah[1], ah[2], ah[3],
                             bhf[ni >> 1][(ni & 1) * 2], bhf[ni >> 1][(ni & 1) * 2 + 1]);
                #pragma unroll
                for (int ni = 0; ni < 4; ni++)
                    MMA16816(acc[mi][ni], ah[0], ah[1], ah[2], ah[3],
                             blf[ni >> 1][(ni & 1) * 2], blf[ni >> 1][(ni & 1) * 2 + 1]);
                #pragma unroll
                for (int ni = 0; ni < 4; ni++)
                    MMA16816(acc[mi][ni], al[0], al[1], al[2], al[3],
                             bhf[ni >> 1][(ni & 1) * 2], bhf[ni >> 1][(ni & 1) * 2 + 1]);
            }
        }

        if (has_next) {
            int nxt = cur ^ 1;
            __nv_bfloat16* d = sm + nxt * SSTG;
            #pragma unroll
            for (int it = 0; it < 2; it++) {
                int so = (it * 64 + lrow) * PITCH + lseg * 8;
                *(uint4*)&d[so] = ra_h[it];
                *(uint4*)&d[OFF_AL + so] = ra_l[it];
            }
            int so = lrow * PITCH + lseg * 8;
            *(uint4*)&d[OFF_BH + so] = rb_h;
            *(uint4*)&d[OFF_BL + so] = rb_l;
            __syncthreads();
            cur = nxt;
        }
    }

    #pragma unroll
    for (int mi = 0; mi < 2; mi++) {
        int row = brow + wm + mi * 16 + g;
        #pragma unroll
        for (int ni = 0; ni < 4; ni++) {
            int col = bn + wn + ni * 8 + 2 * tg;
            if (col < N) {
                float b0 = bias ? bias[col] : 0.f;
                float b1 = bias ? bias[col + 1] : 0.f;
                *(float2*)&C[(long)row * N + col] =
                    make_float2(acc[mi][ni][0] + b0, acc[mi][ni][1] + b1);
                *(float2*)&C[(long)(row + 8) * N + col] =
                    make_float2(acc[mi][ni][2] + b0, acc[mi][ni][3] + b1);
            }
        }
    }
}

// ---------------------------------------------------------------------------
// k_attn: fused attention (unchanged from R13).
// ---------------------------------------------------------------------------
#define ROWS_PER_BLK 8

__global__ __launch_bounds__(256) void k_attn(const float* __restrict__ w3,
                                              const float* __restrict__ bias) {
    __shared__ float fb[S2 * DA];
    __shared__ float bs[DA];
    __shared__ float sc[2][S2];
    __shared__ float inv_s[2];

    int tid = threadIdx.x;
    int b = blockIdx.x, s0 = blockIdx.y * ROWS_PER_BLK;
    int warp = tid >> 5, lane = tid & 31;

    bs[tid] = bias[tid];
    float bs_t = bias[tid];
    float w3r[8];
    #pragma unroll
    for (int j = 0; j < 8; j++) w3r[j] = w3[lane + 32 * j];
    __syncthreads();
    for (int i = tid; i < S2 * DA; i += 256)
        fb[i] = g_f[b * S2 * DA + i] + bs[i & (DA - 1)];
    __syncthreads();

    for (int r = 0; r < ROWS_PER_BLK; r++) {
        int s = s0 + r;
        int pr = r & 1;
        long erow = ((long)b * S1 + s) * DA;

        float ea[8];
        #pragma unroll
        for (int j = 0; j < 8; j++) ea[j] = g_e[erow + lane + 32 * j];

        #pragma unroll
        for (int tt = 0; tt < 5; tt++) {
            int t = warp + 8 * tt;
            float p = 0.f;
            #pragma unroll
            for (int j = 0; j < 8; j++)
                p += fast_tanh(ea[j] + fb[t * DA + lane + 32 * j]) * w3r[j];
            #pragma unroll
            for (int off = 16; off; off >>= 1)
                p += __shfl_xor_sync(0xffffffffu, p, off);
            if (lane == 0) sc[pr][t] = p;
        }
        __syncthreads();

        if (warp == 0) {
            float v0 = sc[pr][lane];
            float v1 = (lane + 32 < S2) ? sc[pr][lane + 32] : -3.4e38f;
            float m = fmaxf(v0, v1);
            #pragma unroll
            for (int off = 16; off; off >>= 1)
                m = fmaxf(m, __shfl_xor_sync(0xffffffffu, m, off));
            float e0 = __expf(v0 - m);
            float e1 = (lane + 32 < S2) ? __expf(v1 - m) : 0.f;
            float su = e0 + e1;
            #pragma unroll
            for (int off = 16; off; off >>= 1)
                su += __shfl_xor_sync(0xffffffffu, su, off);
            sc[pr][lane] = e0;
            if (lane + 32 < S2) sc[pr][lane + 32] = e1;
            if (lane == 0) inv_s[pr] = 1.f / su;
        }
        __syncthreads();

        float acc = 0.f;
        #pragma unroll 8
        for (int t = 0; t < S2; t++)
            acc += sc[pr][t] * fb[t * DA + tid];
        float ta = acc * inv_s[pr] - bs_t;
        float ev = ea[warp];

        long go = ((long)b * S1 + s) * (4 * DA) + tid;
        float vals[4] = {fast_tanh(ev), fast_tanh(ta),
                         fast_tanh(ev * ta), fast_tanh(ev - ta)};
        #pragma unroll
        for (int q = 0; q < 4; q++) {
            __nv_bfloat16 h = __float2bfloat16(vals[q]);
            g_gh[go + q * DA] = h;
            g_gl[go + q * DA] = __float2bfloat16(vals[q] - __bfloat162float(h));
        }
    }
}

// ---------------------------------------------------------------------------
extern "C" void kernel_launch(void* const* d_in, const int* in_sizes, int n_in,
                              void* d_out, int out_size) {
    const float* video = (const float*)d_in[0];
    const float* text  = (const float*)d_in[1];
    const float* w1    = (const float*)d_in[2];
    const float* w2    = (const float*)d_in[3];
    const float* w3    = (const float*)d_in[4];
    const float* bias  = (const float*)d_in[5];
    const float* w4    = (const float*)d_in[6];
    const float* b4    = (const float*)d_in[7];
    float* out = (float*)d_out;

    float* pe;
    __nv_bfloat16 *pvh, *pvl, *pgh, *pgl, *p1h, *p1l, *p4h, *p4l;
    cudaGetSymbolAddress((void**)&pe, g_e);
    cudaGetSymbolAddress((void**)&pvh, g_vh);
    cudaGetSymbolAddress((void**)&pvl, g_vl);
    cudaGetSymbolAddress((void**)&pgh, g_gh);
    cudaGetSymbolAddress((void**)&pgl, g_gl);
    cudaGetSymbolAddress((void**)&p1h, g_w1h);
    cudaGetSymbolAddress((void**)&p1l, g_w1l);
    cudaGetSymbolAddress((void**)&p4h, g_w4h);
    cudaGetSymbolAddress((void**)&p4l, g_w4l);

    cudaFuncSetAttribute(k_gemm_mma, cudaFuncAttributeMaxDynamicSharedMemorySize,
                         GSMEM);

    // fused prologue (coalesced weight transposes)
    k_pre<<<NBLK_W1T + NBLK_W4T + NBLK_V + NBLK_T, 256>>>(w1, w4, video, text, w2);
    // e = video @ w1  (8192x256, K=1024)
    k_gemm_mma<<<dim3((NB * S1) / 128, DA / 64), 256, GSMEM>>>(
        pvh, pvl, p1h, p1l, nullptr, pe, DA, DV);
    // fused attention -> g (split bf16)
    k_attn<<<dim3(NB, S1 / ROWS_PER_BLK), 256>>>(w3, bias);
    // out = g @ w4 + b4  (8192x500, K=1024)
    k_gemm_mma<<<dim3((NB * S1) / 128, DO_PAD / 64), 256, GSMEM>>>(
        pgh, pgl, p4h, p4l, b4, out, DO, 4 * DA);
}